// round 12
// baseline (speedup 1.0000x reference)
#include <cuda_runtime.h>
#include <cuda_bf16.h>
#include <math.h>

#define NN 20000
#define NE 320000
#define HD 512
#define NG 64
#define CAP 64            // direct-indexed CSR capacity per node (Poisson(16): safe)
#define NKC 37            // K-chunks
#define KC16 34           // k16 steps per chunk
#define KCN (KC16 * 16)   // 544 nodes per chunk; 37*544 = 20128 >= 20000
#define NCB 4             // column blocks of 128
#define RPB 157           // w-table rows per reduce block (128*157 >= 20000)
#define GRID 148
#define THREADS 256
#define GSTRIDE (GRID * THREADS)

// ---------------- device scratch ----------------
// single zero-init region: [w-table NN*32][degree NN][wsum 32][barrier 1]
__device__ unsigned g_zero[NN * 32 + NN + 32 + 1];
#define g_w    (g_zero)
#define g_deg  (g_zero + NN * 32)
#define g_wsum (g_zero + NN * 32 + NN)
#define g_bar  (g_zero + NN * 32 + NN + 32)

__device__ int      g_dstBySrc[NN * CAP];   // direct-indexed CSR (5.1 MB)
__device__ unsigned g_vb[NN * 32];          // v as packed bf16x2 (graphs 2w, 2w+1)
__device__ int      g_nn[NG];               // n_g
__device__ float    g_part[(size_t)(NKC * NCB) * NG * 128];
__device__ float    g_U[NG * HD], g_P[NG * HD], g_pooled[NG * HD];

__device__ __forceinline__ unsigned pk16(unsigned short lo, unsigned short hi) {
    return (unsigned)lo | ((unsigned)hi << 16);
}

__device__ __forceinline__ int lbound(const int* a, int n, int v) {
    int lo = 0, hi = n;
    while (lo < hi) { int mid = (lo + hi) >> 1; if (a[mid] < v) lo = mid + 1; else hi = mid; }
    return lo;
}

// grid-wide barrier: monotone counter; all GRID blocks co-resident by construction
__device__ __forceinline__ void gsync(int phase) {
    __threadfence();
    __syncthreads();
    if (threadIdx.x == 0) {
        atomicAdd((unsigned*)g_bar, 1u);
        unsigned target = (unsigned)(GRID * phase);
        unsigned v;
        do {
            asm volatile("ld.global.acquire.gpu.u32 %0, [%1];" : "=r"(v) : "l"((unsigned*)g_bar));
        } while (v < target);
        __threadfence();
    }
    __syncthreads();
}

// ---------------- THE megakernel ----------------
__global__ void __launch_bounds__(THREADS) k_all(
    const float* __restrict__ x, const int* __restrict__ ei, const int* __restrict__ batch,
    const float* __restrict__ W_g1, const float* __restrict__ b_g1,
    const float* __restrict__ W_g2, const float* __restrict__ b_g2,
    const float* __restrict__ W_c1, const float* __restrict__ b_c1,
    const float* __restrict__ W_c2, const float* __restrict__ b_c2,
    float* __restrict__ out)
{
    __shared__ __align__(16) unsigned char s_u[21664];   // phase-union shared
    const int bid = blockIdx.x;
    const int tid = threadIdx.x;
    const int gid = bid * THREADS + tid;
    const int* __restrict__ src = ei;
    const int* __restrict__ dst = ei + NE;

    // ===== phase 0: hist + direct CSR fill =====
    for (int e = gid; e < NE; e += GSTRIDE) {
        int s = src[e];
        int d = dst[e];
        int gb = batch[d];
        unsigned slot = atomicAdd(&g_deg[s], 1u);
        if (slot < CAP) g_dstBySrc[s * CAP + slot] = d;
        atomicAdd(&g_w[s * 32 + (gb >> 1)], 1u << ((gb & 1) * 16));
    }
    for (int i = gid; i < NN; i += GSTRIDE) {
        int gb = batch[i];
        atomicAdd(&g_w[i * 32 + (gb >> 1)], 1u << ((gb & 1) * 16));
    }
    gsync(1);

    // ===== phase 1: v gather (warp per node) =====
    {
        int lane = tid & 31;
        int gwarp = (gid >> 5);                  // 0..1183
        for (int i = gwarp; i < NN; i += GRID * (THREADS / 32)) {
            const unsigned* __restrict__ w = g_w;
            unsigned a = w[(size_t)i * 32 + lane];
            unsigned b = 0, c = 0, d = 0;
            int n = (int)g_deg[i]; if (n > CAP) n = CAP;
            const int* __restrict__ lst = g_dstBySrc + (size_t)i * CAP;
            int f = 0;
            for (; f + 4 <= n; f += 4) {
                int d0 = lst[f], d1 = lst[f + 1], d2 = lst[f + 2], d3 = lst[f + 3];
                a += w[(size_t)d0 * 32 + lane];
                b += w[(size_t)d1 * 32 + lane];
                c += w[(size_t)d2 * 32 + lane];
                d += w[(size_t)d3 * 32 + lane];
            }
            for (; f < n; f++) a += w[(size_t)lst[f] * 32 + lane];
            unsigned tot = a + b + c + d;
            unsigned short hl = __bfloat16_as_ushort(__float2bfloat16((float)(tot & 0xFFFFu)));
            unsigned short hh = __bfloat16_as_ushort(__float2bfloat16((float)(tot >> 16)));
            g_vb[(size_t)i * 32 + lane] = pk16(hl, hh);
        }
    }
    gsync(2);

    // ===== phase 2: tensor-core U-GEMM (148 blocks = 37 kc x 4 cb) =====
    {
        unsigned short* sv  = (unsigned short*)s_u;            // [2][16][66]
        unsigned short* sxh = (unsigned short*)(s_u + 4224);   // [2][16][136]
        unsigned short* sxl = (unsigned short*)(s_u + 12928);  // [2][16][136]
#define SV(b_, k_, g_)  sv[((b_) * 16 + (k_)) * 66 + (g_)]
#define SXH(b_, k_, c_) sxh[((b_) * 16 + (k_)) * 136 + (c_)]
#define SXL(b_, k_, c_) sxl[((b_) * 16 + (k_)) * 136 + (c_)]
        int kc = bid >> 2;
        int cb = bid & 3;
        int warp = tid >> 5, lane = tid & 31;
        int wm = warp >> 1, wn = warp & 1;
        int t4 = lane & 3, gdq = lane >> 2;
        int c2 = t4 * 2;

        float acc[8][4];
#pragma unroll
        for (int i = 0; i < 8; i++) {
            acc[i][0] = 0.f; acc[i][1] = 0.f; acc[i][2] = 0.f; acc[i][3] = 0.f;
        }

        int k0 = kc * KCN;
        int xk = tid >> 4;
        int xn = (tid & 15) * 8;
        const float* xbase = x + (size_t)cb * 128 + xn;
        int vrow0 = tid >> 5, vw0 = tid & 31;
        int vrow1 = (tid + 256) >> 5, vw1 = tid & 31;

        float4 xr0, xr1, xp0, xp1;
        unsigned vr0, vr1, vp0, vp1;

        {
            int kk = k0 + xk;
            if (kk < NN) {
                const float4* p = (const float4*)(xbase + (size_t)kk * HD);
                xr0 = p[0]; xr1 = p[1];
            } else { xr0 = make_float4(0.f,0.f,0.f,0.f); xr1 = xr0; }
            int ka = k0 + vrow0, kb = k0 + vrow1;
            vr0 = (ka < NN) ? g_vb[(size_t)ka * 32 + vw0] : 0u;
            vr1 = (kb < NN) ? g_vb[(size_t)kb * 32 + vw1] : 0u;
        }

        for (int t = 0; t < KC16; t++) {
            int buf = t & 1;
            {
                float vals[8] = {xr0.x, xr0.y, xr0.z, xr0.w, xr1.x, xr1.y, xr1.z, xr1.w};
#pragma unroll
                for (int j = 0; j < 8; j++) {
                    float v = vals[j];
                    __nv_bfloat16 h = __float2bfloat16(v);
                    float hf = __bfloat162float(h);
                    __nv_bfloat16 l = __float2bfloat16(v - hf);
                    SXH(buf, xk, xn + j) = __bfloat16_as_ushort(h);
                    SXL(buf, xk, xn + j) = __bfloat16_as_ushort(l);
                }
                *(unsigned*)&SV(buf, vrow0, vw0 * 2) = vr0;
                *(unsigned*)&SV(buf, vrow1, vw1 * 2) = vr1;
            }
            if (t + 1 < KC16) {
                int kk = k0 + (t + 1) * 16 + xk;
                if (kk < NN) {
                    const float4* p = (const float4*)(xbase + (size_t)kk * HD);
                    xp0 = p[0]; xp1 = p[1];
                } else { xp0 = make_float4(0.f,0.f,0.f,0.f); xp1 = xp0; }
                int ka = k0 + (t + 1) * 16 + vrow0, kb = k0 + (t + 1) * 16 + vrow1;
                vp0 = (ka < NN) ? g_vb[(size_t)ka * 32 + vw0] : 0u;
                vp1 = (kb < NN) ? g_vb[(size_t)kb * 32 + vw1] : 0u;
            }
            __syncthreads();

            int g0 = wm * 16 + gdq;
            unsigned a0 = pk16(SV(buf, c2, g0),     SV(buf, c2 + 1, g0));
            unsigned a1 = pk16(SV(buf, c2, g0 + 8), SV(buf, c2 + 1, g0 + 8));
            unsigned a2 = pk16(SV(buf, c2 + 8, g0),     SV(buf, c2 + 9, g0));
            unsigned a3 = pk16(SV(buf, c2 + 8, g0 + 8), SV(buf, c2 + 9, g0 + 8));

#pragma unroll
            for (int slab = 0; slab < 2; slab++) {
#pragma unroll
                for (int tn = 0; tn < 8; tn++) {
                    int nn = wn * 64 + tn * 8 + gdq;
                    unsigned b0, b1;
                    if (slab == 0) {
                        b0 = pk16(SXH(buf, c2, nn),     SXH(buf, c2 + 1, nn));
                        b1 = pk16(SXH(buf, c2 + 8, nn), SXH(buf, c2 + 9, nn));
                    } else {
                        b0 = pk16(SXL(buf, c2, nn),     SXL(buf, c2 + 1, nn));
                        b1 = pk16(SXL(buf, c2 + 8, nn), SXL(buf, c2 + 9, nn));
                    }
                    asm volatile(
                        "mma.sync.aligned.m16n8k16.row.col.f32.bf16.bf16.f32 "
                        "{%0,%1,%2,%3}, {%4,%5,%6,%7}, {%8,%9}, {%0,%1,%2,%3};"
                        : "+f"(acc[tn][0]), "+f"(acc[tn][1]), "+f"(acc[tn][2]), "+f"(acc[tn][3])
                        : "r"(a0), "r"(a1), "r"(a2), "r"(a3), "r"(b0), "r"(b1));
                }
            }
            xr0 = xp0; xr1 = xp1; vr0 = vp0; vr1 = vp1;
        }

        float* P = g_part + (size_t)bid * NG * 128;
#pragma unroll
        for (int tn = 0; tn < 8; tn++) {
            int c = wn * 64 + tn * 8 + c2;
            int g = wm * 16 + gdq;
            *(float2*)&P[g * 128 + c]       = make_float2(acc[tn][0], acc[tn][1]);
            *(float2*)&P[(g + 8) * 128 + c] = make_float2(acc[tn][2], acc[tn][3]);
        }
#undef SV
#undef SXH
#undef SXL
    }
    gsync(3);

    // ===== phase 3: reduce partials -> U, w column-sum, n_g =====
    if (bid < 128) {
        int idx = bid * THREADS + tid;   // 0..32767
        int g = idx >> 9;
        int c = idx & 511;
        int cb = c >> 7, cc = c & 127;
        const float* __restrict__ p = g_part + (size_t)cb * (NG * 128) + g * 128 + cc;
        const size_t stride = (size_t)NCB * NG * 128;
        float s0 = 0.f, s1 = 0.f, s2 = 0.f, s3 = 0.f;
        int kc = 0;
        for (; kc + 4 <= NKC; kc += 4) {
            s0 += p[(size_t)(kc + 0) * stride];
            s1 += p[(size_t)(kc + 1) * stride];
            s2 += p[(size_t)(kc + 2) * stride];
            s3 += p[(size_t)(kc + 3) * stride];
        }
        for (; kc < NKC; kc++) s0 += p[(size_t)kc * stride];
        g_U[idx] = (s0 + s1) + (s2 + s3);

        // packed column-sum of w over this block's row slice (coalesced)
        unsigned (*swp)[32] = (unsigned(*)[32])s_u;
        int r0 = bid * RPB;
        int r1 = r0 + RPB; if (r1 > NN) r1 = NN;
        int word = tid & 31, rsub = tid >> 5;
        unsigned accp = 0;
        for (int r = r0 + rsub; r < r1; r += 8)
            accp += g_w[(size_t)r * 32 + word];
        swp[rsub][word] = accp;
        __syncthreads();
        if (tid < 32) {
            unsigned s = 0;
#pragma unroll
            for (int j = 0; j < 8; j++) s += swp[j][tid];
            atomicAdd(&g_wsum[tid], s);
        }
        if (bid == 0 && tid >= 128 && tid < 128 + NG) {
            int gg = tid - 128;
            int lo = lbound(batch, NN, gg);
            int hi = lbound(batch, NN, gg + 1);
            g_nn[gg] = hi - lo;
        }
    }
    gsync(4);

    // ===== phase 4: P = U @ W1 + (n+m)*b1 =====
    if (bid < 64) {
        float (*sW)[8] = (float(*)[8])s_u;
        int c0 = bid * 8;
        {
            int k = tid * 2;
            const float4* p0 = (const float4*)(W_g1 + (size_t)k * HD + c0);
            const float4* p1 = (const float4*)(W_g1 + (size_t)(k + 1) * HD + c0);
            *(float4*)&sW[k][0] = p0[0];     *(float4*)&sW[k][4] = p0[1];
            *(float4*)&sW[k + 1][0] = p1[0]; *(float4*)&sW[k + 1][4] = p1[1];
        }
        __syncthreads();
        int g = tid >> 2, cp = (tid & 3) * 2;
        float a0 = 0.f, a1 = 0.f;
        const float* inr = g_U + (size_t)g * HD;
#pragma unroll 8
        for (int k = 0; k < HD; k++) {
            float a = inr[k];
            a0 += a * sW[k][cp];
            a1 += a * sW[k][cp + 1];
        }
        float sc = (float)((g_wsum[g >> 1] >> ((g & 1) * 16)) & 0xFFFFu);
        g_P[(size_t)g * HD + c0 + cp]     = a0 + b_g1[c0 + cp] * sc;
        g_P[(size_t)g * HD + c0 + cp + 1] = a1 + b_g1[c0 + cp + 1] * sc;
    }
    gsync(5);

    // ===== phase 5: pooled = P @ W2 + n*b2 =====
    if (bid < 64) {
        float (*sW)[8] = (float(*)[8])s_u;
        int c0 = bid * 8;
        {
            int k = tid * 2;
            const float4* p0 = (const float4*)(W_g2 + (size_t)k * HD + c0);
            const float4* p1 = (const float4*)(W_g2 + (size_t)(k + 1) * HD + c0);
            *(float4*)&sW[k][0] = p0[0];     *(float4*)&sW[k][4] = p0[1];
            *(float4*)&sW[k + 1][0] = p1[0]; *(float4*)&sW[k + 1][4] = p1[1];
        }
        __syncthreads();
        int g = tid >> 2, cp = (tid & 3) * 2;
        float a0 = 0.f, a1 = 0.f;
        const float* inr = g_P + (size_t)g * HD;
#pragma unroll 8
        for (int k = 0; k < HD; k++) {
            float a = inr[k];
            a0 += a * sW[k][cp];
            a1 += a * sW[k][cp + 1];
        }
        float sc = (float)g_nn[g];
        g_pooled[(size_t)g * HD + c0 + cp]     = a0 + b_g2[c0 + cp] * sc;
        g_pooled[(size_t)g * HD + c0 + cp + 1] = a1 + b_g2[c0 + cp + 1] * sc;
    }
    gsync(6);

    // ===== phase 6: classifier head =====
    if (bid < NG) {
        float* sp  = (float*)s_u;              // 512 floats
        float* red = (float*)(s_u + 2048);     // 256 floats
        int g = bid;
        int j = tid;
        for (int k = j; k < HD; k += THREADS) sp[k] = g_pooled[g * HD + k];
        __syncthreads();
        float acc = 0.f;
#pragma unroll 8
        for (int k = 0; k < HD; k++) acc += sp[k] * W_c1[k * 256 + j];
        float zj = fmaxf(acc + b_c1[j], 0.f) * W_c2[j];
        red[j] = zj;
        __syncthreads();
        for (int ofs = 128; ofs > 0; ofs >>= 1) {
            if (j < ofs) red[j] += red[j + ofs];
            __syncthreads();
        }
        if (j == 0) {
            float s = red[0] + b_c2[0];
            out[g] = 1.0f / (1.0f + expf(-s));
        }
    }
}

// ---------------- launch ----------------
extern "C" void kernel_launch(void* const* d_in, const int* in_sizes, int n_in,
                              void* d_out, int out_size) {
    const float* x     = (const float*)d_in[0];
    const int*   ei    = (const int*)d_in[1];
    const int*   batch = (const int*)d_in[2];
    const float* W_g1  = (const float*)d_in[3];
    const float* b_g1  = (const float*)d_in[4];
    const float* W_g2  = (const float*)d_in[5];
    const float* b_g2  = (const float*)d_in[6];
    const float* W_c1  = (const float*)d_in[7];
    const float* b_c1  = (const float*)d_in[8];
    const float* W_c2  = (const float*)d_in[9];
    const float* b_c2  = (const float*)d_in[10];
    float* out = (float*)d_out;

    unsigned* pZero;
    cudaGetSymbolAddress((void**)&pZero, g_zero);
    cudaMemsetAsync(pZero, 0, sizeof(unsigned) * (NN * 32 + NN + 32 + 1));

    k_all<<<GRID, THREADS>>>(x, ei, batch, W_g1, b_g1, W_g2, b_g2,
                             W_c1, b_c1, W_c2, b_c2, out);
}

// round 13
// speedup vs baseline: 1.1910x; 1.1910x over previous
#include <cuda_runtime.h>
#include <cuda_bf16.h>
#include <math.h>

#define NN 20000
#define NE 320000
#define HD 512
#define NG 64
#define CAP 64            // direct-indexed CSR capacity per node (Poisson(16): safe)
#define NKC 37            // K-chunks
#define KC16 34           // k16 steps per chunk
#define KCN (KC16 * 16)   // 544 nodes per chunk; 37*544 = 20128 >= 20000
#define NCB 4             // column blocks of 128
#define RPB 157           // w-table rows per reduce block (128*157 >= 20000)
#define GRID 148
#define THREADS 256

// ---------------- device scratch ----------------
// single zero-init region: [w-table NN*32][degree NN][wsum 32][barrier 1]
__device__ unsigned g_zero[NN * 32 + NN + 32 + 1];
#define g_w    (g_zero)
#define g_deg  (g_zero + NN * 32)
#define g_wsum (g_zero + NN * 32 + NN)
#define g_bar  (g_zero + NN * 32 + NN + 32)

__device__ int      g_dstBySrc[NN * CAP];   // direct-indexed CSR (5.1 MB)
__device__ unsigned g_vb[NN * 32];          // v as packed bf16x2 (graphs 2w, 2w+1)
__device__ int      g_nn[NG];               // n_g
__device__ float    g_part[(size_t)GRID * NG * 128];
__device__ float    g_U[NG * HD], g_P[NG * HD], g_pooled[NG * HD];

__device__ __forceinline__ unsigned pk16(unsigned short lo, unsigned short hi) {
    return (unsigned)lo | ((unsigned)hi << 16);
}

__device__ __forceinline__ int lbound(const int* a, int n, int v) {
    int lo = 0, hi = n;
    while (lo < hi) { int mid = (lo + hi) >> 1; if (a[mid] < v) lo = mid + 1; else hi = mid; }
    return lo;
}

// grid-wide barrier among GRID co-resident blocks (1 CTA/SM guaranteed)
__device__ __forceinline__ void gsync(int phase) {
    __threadfence();
    __syncthreads();
    if (threadIdx.x == 0) {
        atomicAdd((unsigned*)g_bar, 1u);
        unsigned target = (unsigned)(GRID * phase);
        unsigned v;
        do {
            asm volatile("ld.global.acquire.gpu.u32 %0, [%1];" : "=r"(v) : "l"((unsigned*)g_bar));
        } while (v < target);
        __threadfence();
    }
    __syncthreads();
}

// ---------------- 1. hist + direct CSR fill (wide launch, unchanged) ----------------
__global__ void k_hist(const int* __restrict__ src, const int* __restrict__ dst,
                       const int* __restrict__ batch) {
    int e = blockIdx.x * blockDim.x + threadIdx.x;
    if (e < NE) {
        int s = src[e];
        int d = dst[e];
        int gb = batch[d];
        unsigned slot = atomicAdd(&g_deg[s], 1u);
        if (slot < CAP) g_dstBySrc[s * CAP + slot] = d;
        atomicAdd(&g_w[s * 32 + (gb >> 1)], 1u << ((gb & 1) * 16));
    }
    if (e < NN) {
        int gb = batch[e];
        atomicAdd(&g_w[e * 32 + (gb >> 1)], 1u << ((gb & 1) * 16));
    }
}

// ---------------- 2. v gather (wide launch, warp per node, unchanged) ----------------
__global__ void __launch_bounds__(256) k_vgather() {
    int i = (blockIdx.x * 256 + threadIdx.x) >> 5;
    int lane = threadIdx.x & 31;
    if (i >= NN) return;
    const unsigned* __restrict__ w = g_w;
    unsigned a = w[(size_t)i * 32 + lane];
    unsigned b = 0, c = 0, d = 0;
    int n = (int)g_deg[i]; if (n > CAP) n = CAP;
    const int* __restrict__ lst = g_dstBySrc + (size_t)i * CAP;
    int f = 0;
    for (; f + 4 <= n; f += 4) {
        int d0 = lst[f], d1 = lst[f + 1], d2 = lst[f + 2], d3 = lst[f + 3];
        a += w[(size_t)d0 * 32 + lane];
        b += w[(size_t)d1 * 32 + lane];
        c += w[(size_t)d2 * 32 + lane];
        d += w[(size_t)d3 * 32 + lane];
    }
    for (; f < n; f++) a += w[(size_t)lst[f] * 32 + lane];
    unsigned tot = a + b + c + d;
    unsigned short hl = __bfloat16_as_ushort(__float2bfloat16((float)(tot & 0xFFFFu)));
    unsigned short hh = __bfloat16_as_ushort(__float2bfloat16((float)(tot >> 16)));
    g_vb[(size_t)i * 32 + lane] = pk16(hl, hh);
}

// ---------------- 3. fused persistent tail: gemm -> reduce -> mmT1 -> mmT2 -> head ----------------
__global__ void __launch_bounds__(THREADS) k_fused(
    const float* __restrict__ x, const int* __restrict__ batch,
    const float* __restrict__ W_g1, const float* __restrict__ b_g1,
    const float* __restrict__ W_g2, const float* __restrict__ b_g2,
    const float* __restrict__ W_c1, const float* __restrict__ b_c1,
    const float* __restrict__ W_c2, const float* __restrict__ b_c2,
    float* __restrict__ out)
{
    __shared__ __align__(16) unsigned char s_u[21664];
    const int bid = blockIdx.x;
    const int tid = threadIdx.x;

    // ===== phase A: tensor-core U-GEMM (exactly 148 blocks = 37 kc x 4 cb) =====
    {
        unsigned short* sv  = (unsigned short*)s_u;            // [2][16][66]
        unsigned short* sxh = (unsigned short*)(s_u + 4224);   // [2][16][136]
        unsigned short* sxl = (unsigned short*)(s_u + 12928);  // [2][16][136]
#define SV(b_, k_, g_)  sv[((b_) * 16 + (k_)) * 66 + (g_)]
#define SXH(b_, k_, c_) sxh[((b_) * 16 + (k_)) * 136 + (c_)]
#define SXL(b_, k_, c_) sxl[((b_) * 16 + (k_)) * 136 + (c_)]
        int kc = bid >> 2;
        int cb = bid & 3;
        int warp = tid >> 5, lane = tid & 31;
        int wm = warp >> 1, wn = warp & 1;
        int t4 = lane & 3, gdq = lane >> 2;
        int c2 = t4 * 2;

        float acc[8][4];
#pragma unroll
        for (int i = 0; i < 8; i++) {
            acc[i][0] = 0.f; acc[i][1] = 0.f; acc[i][2] = 0.f; acc[i][3] = 0.f;
        }

        int k0 = kc * KCN;
        int xk = tid >> 4;
        int xn = (tid & 15) * 8;
        const float* xbase = x + (size_t)cb * 128 + xn;
        int vrow0 = tid >> 5, vw0 = tid & 31;
        int vrow1 = (tid + 256) >> 5, vw1 = tid & 31;

        float4 xr0, xr1, xp0, xp1;
        unsigned vr0, vr1, vp0, vp1;

        {
            int kk = k0 + xk;
            if (kk < NN) {
                const float4* p = (const float4*)(xbase + (size_t)kk * HD);
                xr0 = p[0]; xr1 = p[1];
            } else { xr0 = make_float4(0.f,0.f,0.f,0.f); xr1 = xr0; }
            int ka = k0 + vrow0, kb = k0 + vrow1;
            vr0 = (ka < NN) ? g_vb[(size_t)ka * 32 + vw0] : 0u;
            vr1 = (kb < NN) ? g_vb[(size_t)kb * 32 + vw1] : 0u;
        }

        for (int t = 0; t < KC16; t++) {
            int buf = t & 1;
            {
                float vals[8] = {xr0.x, xr0.y, xr0.z, xr0.w, xr1.x, xr1.y, xr1.z, xr1.w};
#pragma unroll
                for (int j = 0; j < 8; j++) {
                    float v = vals[j];
                    __nv_bfloat16 h = __float2bfloat16(v);
                    float hf = __bfloat162float(h);
                    __nv_bfloat16 l = __float2bfloat16(v - hf);
                    SXH(buf, xk, xn + j) = __bfloat16_as_ushort(h);
                    SXL(buf, xk, xn + j) = __bfloat16_as_ushort(l);
                }
                *(unsigned*)&SV(buf, vrow0, vw0 * 2) = vr0;
                *(unsigned*)&SV(buf, vrow1, vw1 * 2) = vr1;
            }
            if (t + 1 < KC16) {
                int kk = k0 + (t + 1) * 16 + xk;
                if (kk < NN) {
                    const float4* p = (const float4*)(xbase + (size_t)kk * HD);
                    xp0 = p[0]; xp1 = p[1];
                } else { xp0 = make_float4(0.f,0.f,0.f,0.f); xp1 = xp0; }
                int ka = k0 + (t + 1) * 16 + vrow0, kb = k0 + (t + 1) * 16 + vrow1;
                vp0 = (ka < NN) ? g_vb[(size_t)ka * 32 + vw0] : 0u;
                vp1 = (kb < NN) ? g_vb[(size_t)kb * 32 + vw1] : 0u;
            }
            __syncthreads();

            int g0 = wm * 16 + gdq;
            unsigned a0 = pk16(SV(buf, c2, g0),     SV(buf, c2 + 1, g0));
            unsigned a1 = pk16(SV(buf, c2, g0 + 8), SV(buf, c2 + 1, g0 + 8));
            unsigned a2 = pk16(SV(buf, c2 + 8, g0),     SV(buf, c2 + 9, g0));
            unsigned a3 = pk16(SV(buf, c2 + 8, g0 + 8), SV(buf, c2 + 9, g0 + 8));

#pragma unroll
            for (int slab = 0; slab < 2; slab++) {
#pragma unroll
                for (int tn = 0; tn < 8; tn++) {
                    int nn = wn * 64 + tn * 8 + gdq;
                    unsigned b0, b1;
                    if (slab == 0) {
                        b0 = pk16(SXH(buf, c2, nn),     SXH(buf, c2 + 1, nn));
                        b1 = pk16(SXH(buf, c2 + 8, nn), SXH(buf, c2 + 9, nn));
                    } else {
                        b0 = pk16(SXL(buf, c2, nn),     SXL(buf, c2 + 1, nn));
                        b1 = pk16(SXL(buf, c2 + 8, nn), SXL(buf, c2 + 9, nn));
                    }
                    asm volatile(
                        "mma.sync.aligned.m16n8k16.row.col.f32.bf16.bf16.f32 "
                        "{%0,%1,%2,%3}, {%4,%5,%6,%7}, {%8,%9}, {%0,%1,%2,%3};"
                        : "+f"(acc[tn][0]), "+f"(acc[tn][1]), "+f"(acc[tn][2]), "+f"(acc[tn][3])
                        : "r"(a0), "r"(a1), "r"(a2), "r"(a3), "r"(b0), "r"(b1));
                }
            }
            xr0 = xp0; xr1 = xp1; vr0 = vp0; vr1 = vp1;
        }

        float* P = g_part + (size_t)bid * NG * 128;
#pragma unroll
        for (int tn = 0; tn < 8; tn++) {
            int c = wn * 64 + tn * 8 + c2;
            int g = wm * 16 + gdq;
            *(float2*)&P[g * 128 + c]       = make_float2(acc[tn][0], acc[tn][1]);
            *(float2*)&P[(g + 8) * 128 + c] = make_float2(acc[tn][2], acc[tn][3]);
        }
#undef SV
#undef SXH
#undef SXL
    }
    gsync(1);

    // ===== phase B: reduce partials -> U, w column-sum, n_g =====
    if (bid < 128) {
        int idx = bid * THREADS + tid;   // 0..32767
        int g = idx >> 9;
        int c = idx & 511;
        int cb = c >> 7, cc = c & 127;
        const float* __restrict__ p = g_part + (size_t)cb * (NG * 128) + g * 128 + cc;
        const size_t stride = (size_t)NCB * NG * 128;
        float s0 = 0.f, s1 = 0.f, s2 = 0.f, s3 = 0.f;
        int kc = 0;
        for (; kc + 4 <= NKC; kc += 4) {
            s0 += p[(size_t)(kc + 0) * stride];
            s1 += p[(size_t)(kc + 1) * stride];
            s2 += p[(size_t)(kc + 2) * stride];
            s3 += p[(size_t)(kc + 3) * stride];
        }
        for (; kc < NKC; kc++) s0 += p[(size_t)kc * stride];
        g_U[idx] = (s0 + s1) + (s2 + s3);

        unsigned (*swp)[32] = (unsigned(*)[32])s_u;
        int r0 = bid * RPB;
        int r1 = r0 + RPB; if (r1 > NN) r1 = NN;
        int word = tid & 31, rsub = tid >> 5;
        unsigned accp = 0;
        for (int r = r0 + rsub; r < r1; r += 8)
            accp += g_w[(size_t)r * 32 + word];
        swp[rsub][word] = accp;
        __syncthreads();
        if (tid < 32) {
            unsigned s = 0;
#pragma unroll
            for (int j = 0; j < 8; j++) s += swp[j][tid];
            atomicAdd(&g_wsum[tid], s);
        }
        if (bid == 0 && tid >= 128 && tid < 128 + NG) {
            int gg = tid - 128;
            int lo = lbound(batch, NN, gg);
            int hi = lbound(batch, NN, gg + 1);
            g_nn[gg] = hi - lo;
        }
    }
    gsync(2);

    // ===== phase C: P = U @ W1 + (n+m)*b1 =====
    if (bid < 64) {
        float (*sW)[8] = (float(*)[8])s_u;
        int c0 = bid * 8;
        {
            int k = tid * 2;
            const float4* p0 = (const float4*)(W_g1 + (size_t)k * HD + c0);
            const float4* p1 = (const float4*)(W_g1 + (size_t)(k + 1) * HD + c0);
            *(float4*)&sW[k][0] = p0[0];     *(float4*)&sW[k][4] = p0[1];
            *(float4*)&sW[k + 1][0] = p1[0]; *(float4*)&sW[k + 1][4] = p1[1];
        }
        __syncthreads();
        int g = tid >> 2, cp = (tid & 3) * 2;
        float a0 = 0.f, a1 = 0.f;
        const float* inr = g_U + (size_t)g * HD;
#pragma unroll 8
        for (int k = 0; k < HD; k++) {
            float a = inr[k];
            a0 += a * sW[k][cp];
            a1 += a * sW[k][cp + 1];
        }
        float sc = (float)((g_wsum[g >> 1] >> ((g & 1) * 16)) & 0xFFFFu);
        g_P[(size_t)g * HD + c0 + cp]     = a0 + b_g1[c0 + cp] * sc;
        g_P[(size_t)g * HD + c0 + cp + 1] = a1 + b_g1[c0 + cp + 1] * sc;
    }
    gsync(3);

    // ===== phase D: pooled = P @ W2 + n*b2 =====
    if (bid < 64) {
        float (*sW)[8] = (float(*)[8])s_u;
        int c0 = bid * 8;
        {
            int k = tid * 2;
            const float4* p0 = (const float4*)(W_g2 + (size_t)k * HD + c0);
            const float4* p1 = (const float4*)(W_g2 + (size_t)(k + 1) * HD + c0);
            *(float4*)&sW[k][0] = p0[0];     *(float4*)&sW[k][4] = p0[1];
            *(float4*)&sW[k + 1][0] = p1[0]; *(float4*)&sW[k + 1][4] = p1[1];
        }
        __syncthreads();
        int g = tid >> 2, cp = (tid & 3) * 2;
        float a0 = 0.f, a1 = 0.f;
        const float* inr = g_P + (size_t)g * HD;
#pragma unroll 8
        for (int k = 0; k < HD; k++) {
            float a = inr[k];
            a0 += a * sW[k][cp];
            a1 += a * sW[k][cp + 1];
        }
        float sc = (float)g_nn[g];
        g_pooled[(size_t)g * HD + c0 + cp]     = a0 + b_g2[c0 + cp] * sc;
        g_pooled[(size_t)g * HD + c0 + cp + 1] = a1 + b_g2[c0 + cp + 1] * sc;
    }
    gsync(4);

    // ===== phase E: classifier head =====
    if (bid < NG) {
        float* sp  = (float*)s_u;
        float* red = (float*)(s_u + 2048);
        int g = bid;
        int j = tid;
        for (int k = j; k < HD; k += THREADS) sp[k] = g_pooled[g * HD + k];
        __syncthreads();
        float acc = 0.f;
#pragma unroll 8
        for (int k = 0; k < HD; k++) acc += sp[k] * W_c1[k * 256 + j];
        float zj = fmaxf(acc + b_c1[j], 0.f) * W_c2[j];
        red[j] = zj;
        __syncthreads();
        for (int ofs = 128; ofs > 0; ofs >>= 1) {
            if (j < ofs) red[j] += red[j + ofs];
            __syncthreads();
        }
        if (j == 0) {
            float s = red[0] + b_c2[0];
            out[g] = 1.0f / (1.0f + expf(-s));
        }
    }
}

// ---------------- launch ----------------
extern "C" void kernel_launch(void* const* d_in, const int* in_sizes, int n_in,
                              void* d_out, int out_size) {
    const float* x     = (const float*)d_in[0];
    const int*   ei    = (const int*)d_in[1];
    const int*   batch = (const int*)d_in[2];
    const float* W_g1  = (const float*)d_in[3];
    const float* b_g1  = (const float*)d_in[4];
    const float* W_g2  = (const float*)d_in[5];
    const float* b_g2  = (const float*)d_in[6];
    const float* W_c1  = (const float*)d_in[7];
    const float* b_c1  = (const float*)d_in[8];
    const float* W_c2  = (const float*)d_in[9];
    const float* b_c2  = (const float*)d_in[10];
    float* out = (float*)d_out;

    const int* src = ei;
    const int* dst = ei + NE;

    unsigned* pZero;
    cudaGetSymbolAddress((void**)&pZero, g_zero);
    cudaMemsetAsync(pZero, 0, sizeof(unsigned) * (NN * 32 + NN + 32 + 1));

    k_hist<<<(NE + 255) / 256, 256>>>(src, dst, batch);
    k_vgather<<<(NN * 32 + 255) / 256, 256>>>();
    k_fused<<<GRID, THREADS>>>(x, batch, W_g1, b_g1, W_g2, b_g2,
                               W_c1, b_c1, W_c2, b_c2, out);
}